// round 15
// baseline (speedup 1.0000x reference)
#include <cuda_runtime.h>
#include <cuda_fp16.h>
#include <cstdint>

#define N_TOK 512
#define E_DIM 256
#define HID   150
#define NP    152
#define W64ST 164            // weight pair-row stride in uint64 (164 % 16 == 4)
#define CHUNKW 2624          // 8 pair-rows * 328 words per 16-kpair chunk
#define CHUNK4 656           // CHUNKW / 4
#define PST   136            // P word stride (pair-interleaved, 68 u64, 68%16==4)
#define H1ST  104            // h1 word stride (52 u64, 52%16==4)
#define IMG1W (8 * CHUNKW)   // 20992 words
#define IMG2W (5 * CHUNKW)   // 13120 words

__device__ float    g_sA[N_TOK * NP];
__device__ float    g_sB[N_TOK * NP];
__device__ uint32_t g_img1[IMG1W];
__device__ uint32_t g_img2[IMG2W];

// ---------------- SMEM layout (bytes) ----------------
#define OFF_P    0                       // P: 128 x 136 words (69632 B); h1 aliases
#define OFF_W    69632                   // weight double buffer 2 x 2624 words (20992 B)
#define OFF_X    90624                   // gih/gjh (12416 B) then sA/sB (14592 B)
#define OFF_B2   105216
#define OFF_W3   105824
#define OFF_MSI  106432
#define OFF_MSJ  106496
#define OFF_PART 106528                  // 128 x 2 floats
#define OFF_B3   107552
#define PW_SMEM  107584

// ---------------- helpers ----------------
__device__ __forceinline__ uint32_t packh2(float lo, float hi) {
    __half2 h = __floats2half2_rn(lo, hi);
    return *reinterpret_cast<uint32_t*>(&h);
}
__device__ __forceinline__ uint32_t hmul2u(uint32_t a, uint32_t b) {
    __half2 r = __hmul2(*reinterpret_cast<__half2*>(&a), *reinterpret_cast<__half2*>(&b));
    return *reinterpret_cast<uint32_t*>(&r);
}
__device__ __forceinline__ void mma16(float* d, uint32_t a0, uint32_t a1,
                                      uint32_t a2, uint32_t a3,
                                      uint32_t b0, uint32_t b1) {
    asm volatile(
        "mma.sync.aligned.m16n8k16.row.col.f32.f16.f16.f32 "
        "{%0,%1,%2,%3}, {%4,%5,%6,%7}, {%8,%9}, {%0,%1,%2,%3};"
        : "+f"(d[0]), "+f"(d[1]), "+f"(d[2]), "+f"(d[3])
        : "r"(a0), "r"(a1), "r"(a2), "r"(a3), "r"(b0), "r"(b1));
}
__device__ __forceinline__ void cpasync16(uint32_t dst, const float4* src) {
    asm volatile("cp.async.cg.shared.global [%0], [%1], 16;" :: "r"(dst), "l"(src));
}
#define CP_COMMIT() asm volatile("cp.async.commit_group;")
#define CP_WAIT0()  asm volatile("cp.async.wait_group 0;" ::: "memory")

__device__ __forceinline__ void stage_chunk(uint32_t smem_dst, const float4* src, int tid) {
    #pragma unroll
    for (int t = 0; t < 3; t++) {
        int idx = tid + t * 256;
        if (idx < CHUNK4) cpasync16(smem_dst + idx * 16, src + idx);
    }
    CP_COMMIT();
}

// ---------------------------------------------------------------------------
// prep: one wave, 210 blocks.
//   blocks 0..127 : sA/sB precompute (identical to R14 — bit-identical output)
//   blocks 128..209: pair-interleaved fp16 weight image build
//     word idx -> chunk c = idx/CHUNKW, pair-row pr = rem/328, off = rem%328,
//     n = off>>1, hi = off&1, kp = c*16 + (pr>>2)*8 + (pr&3) + hi*4
// ---------------------------------------------------------------------------
struct SmemAB { float g[8][E_DIM]; float w[32][160]; };

__global__ __launch_bounds__(256, 2)
void prep(const float* __restrict__ G, const float* __restrict__ W1,
          const float* __restrict__ W2, const float* __restrict__ b1) {
    const int bid = blockIdx.x, tid = threadIdx.x;

    if (bid >= 128) {
        int idx = (bid - 128) * 256 + tid;
        if (idx < IMG1W) {
            int c = idx / CHUNKW, rem = idx - c * CHUNKW;
            int pr = rem / 328, off = rem - pr * 328;
            int n = off >> 1, hi = off & 1;
            int kp = c * 16 + (pr >> 2) * 8 + (pr & 3) + hi * 4;
            float vlo = 0.f, vhi = 0.f;
            if (n < HID) {
                vlo = W1[(2 * E_DIM + 2 * kp)     * HID + n];
                vhi = W1[(2 * E_DIM + 2 * kp + 1) * HID + n];
            }
            g_img1[idx] = packh2(vlo, vhi);
        }
        if (idx < IMG2W) {
            int c = idx / CHUNKW, rem = idx - c * CHUNKW;
            int pr = rem / 328, off = rem - pr * 328;
            int n = off >> 1, hi = off & 1;
            int kp = c * 16 + (pr >> 2) * 8 + (pr & 3) + hi * 4;
            float vlo = 0.f, vhi = 0.f;
            if (n < HID) {
                if (2 * kp     < HID) vlo = W2[(2 * kp)     * HID + n];
                if (2 * kp + 1 < HID) vhi = W2[(2 * kp + 1) * HID + n];
            }
            g_img2[idx] = packh2(vlo, vhi);
        }
        return;
    }

    // ---- sA/sB precompute: 8 rows/block (identical to R14) ----
    extern __shared__ char smemraw[];
    SmemAB& s = *reinterpret_cast<SmemAB*>(smemraw);
    const int tx = tid & 31, ty = tid >> 5;
    const int r0 = (bid >> 1) * 8, variant = bid & 1;
    const float* W = W1 + variant * E_DIM * HID;
    float* outbuf = variant ? g_sB : g_sA;

    for (int idx = tid; idx < 8 * E_DIM; idx += 256)
        s.g[idx >> 8][idx & 255] = G[(r0 + (idx >> 8)) * E_DIM + (idx & 255)];

    float acc[5];
    #pragma unroll
    for (int n = 0; n < 5; n++) {
        int h = tx * 5 + n;
        acc[n] = (variant == 0 && h < HID) ? b1[h] : 0.f;
    }
    for (int kk = 0; kk < E_DIM; kk += 32) {
        __syncthreads();
        for (int idx = tid; idx < 32 * 160; idx += 256) {
            int r = idx / 160, c = idx - r * 160;
            s.w[r][c] = (c < HID) ? W[(kk + r) * HID + c] : 0.f;
        }
        __syncthreads();
        #pragma unroll 8
        for (int e = 0; e < 32; e++) {
            float a = s.g[ty][kk + e];
            float w[5];
            #pragma unroll
            for (int n = 0; n < 5; n++) w[n] = s.w[e][tx * 5 + n];
            #pragma unroll
            for (int n = 0; n < 5; n++)
                acc[n] = fmaf(a, w[n], acc[n]);
        }
    }
    {
        int r = r0 + ty;
        #pragma unroll
        for (int n = 0; n < 5; n++) {
            int h = tx * 5 + n;
            if (h < NP) outbuf[r * NP + h] = acc[n];
        }
    }
}

// ---------------------------------------------------------------------------
// pw_body: templated on NF. Same schedule/syncs as R10/R14; fragment loads
// are now LDS.64 on pair-interleaved layouts (values bit-identical).
// ---------------------------------------------------------------------------
template<int NF>
__device__ __forceinline__ void pw_body(
    char* sm, uint32_t sb, int tid, int wm, int wn, int qrow, int qk,
    int i0, int j0, float* __restrict__ out)
{
    uint32_t* P  = (uint32_t*)sm;
    uint32_t* h1 = (uint32_t*)sm;
    float* sA   = (float*)(sm + OFF_X);
    float* sB   = sA + 16 * NP;
    float* s_b2 = (float*)(sm + OFF_B2);
    float* s_w3 = (float*)(sm + OFF_W3);
    float* msi  = (float*)(sm + OFF_MSI);
    float* msj  = (float*)(sm + OFF_MSJ);
    float* part = (float*)(sm + OFF_PART);
    const int nbase = wn * 80;
    const uint32_t wsm[2] = { sb + OFF_W, sb + OFF_W + CHUNKW * 4 };

    float acc[2][NF][4];
    #pragma unroll
    for (int fm = 0; fm < 2; fm++)
        #pragma unroll
        for (int nf = 0; nf < NF; nf++)
            #pragma unroll
            for (int q = 0; q < 4; q++) acc[fm][nf][q] = 0.f;

    const float4* img1_4 = (const float4*)g_img1;
    const float4* img2_4 = (const float4*)g_img2;

    // ---- GEMM1: acc = P @ W1c^T, K=256 = 8 chunks x 2 k16-tiles ----
    for (int c = 0; c < 8; c++) {
        stage_chunk(wsm[(c + 1) & 1],
                    (c < 7) ? (img1_4 + (c + 1) * CHUNK4) : img2_4, tid);
        const uint32_t* wb = (const uint32_t*)(sm + OFF_W) + (c & 1) * CHUNKW;
        #pragma unroll
        for (int t = 0; t < 2; t++) {
            uint32_t b[NF][2];
            #pragma unroll
            for (int nf = 0; nf < NF; nf++) {
                int n = nbase + nf * 8 + qrow;
                uint2 bv = *(const uint2*)&wb[(t * 4 + qk) * 328 + 2 * n];
                b[nf][0] = bv.x; b[nf][1] = bv.y;
            }
            #pragma unroll
            for (int fm = 0; fm < 2; fm++) {
                int row = wm * 32 + fm * 16 + qrow;
                int widx = row * PST + (c * 2 + t) * 8 + 2 * qk;
                uint2 vA = *(const uint2*)&P[widx];
                uint2 vB = *(const uint2*)&P[widx + 8 * PST];
                #pragma unroll
                for (int nf = 0; nf < NF; nf++)
                    mma16(acc[fm][nf], vA.x, vB.x, vA.y, vB.y, b[nf][0], b[nf][1]);
            }
        }
        CP_WAIT0();
        __syncthreads();
    }

    // ---- h1 = relu(acc + sA_i + sB_j) as half2 (pair-interleaved) ----
    #pragma unroll
    for (int fm = 0; fm < 2; fm++) {
        int r0 = wm * 32 + fm * 16 + qrow, r1 = r0 + 8;
        int il0 = wm * 4 + fm * 2;
        #pragma unroll
        for (int nf = 0; nf < NF; nf++) {
            int c0 = nbase + nf * 8 + 2 * qk, c1 = c0 + 1;
            int hw = (5 * wn + (nf >> 1)) * 8 + 2 * qk + (nf & 1);
            float sb0 = sB[qrow * NP + c0], sb1 = sB[qrow * NP + c1];
            float v00 = acc[fm][nf][0] + sA[il0 * NP + c0] + sb0;
            float v01 = acc[fm][nf][1] + sA[il0 * NP + c1] + sb1;
            float v10 = acc[fm][nf][2] + sA[(il0 + 1) * NP + c0] + sb0;
            float v11 = acc[fm][nf][3] + sA[(il0 + 1) * NP + c1] + sb1;
            h1[r0 * H1ST + hw] = packh2(fmaxf(v00, 0.f), fmaxf(v01, 0.f));
            h1[r1 * H1ST + hw] = packh2(fmaxf(v10, 0.f), fmaxf(v11, 0.f));
            float w0 = s_b2[c0], w1 = s_b2[c1];
            acc[fm][nf][0] = w0; acc[fm][nf][1] = w1;
            acc[fm][nf][2] = w0; acc[fm][nf][3] = w1;
        }
    }
    {   // zero pad words (old 76..79 -> new idx 73/75/77/79 of group 9)
        int r = wm * 32 + (tid & 31);
        h1[r * H1ST + 73] = 0u;
        h1[r * H1ST + 75] = 0u;
        h1[r * H1ST + 77] = 0u;
        h1[r * H1ST + 79] = 0u;
    }
    __syncthreads();   // h1 visible; w buf0 already holds img2 chunk 0

    // ---- GEMM2: acc += h1 @ W2^T, K=160 = 5 chunks x 2 k16-tiles ----
    for (int c = 0; c < 5; c++) {
        if (c < 4) stage_chunk(wsm[(c + 1) & 1], img2_4 + (c + 1) * CHUNK4, tid);
        const uint32_t* wb = (const uint32_t*)(sm + OFF_W) + (c & 1) * CHUNKW;
        #pragma unroll
        for (int t = 0; t < 2; t++) {
            int g = c * 2 + t;
            uint32_t b[NF][2];
            #pragma unroll
            for (int nf = 0; nf < NF; nf++) {
                int n = nbase + nf * 8 + qrow;
                uint2 bv = *(const uint2*)&wb[(t * 4 + qk) * 328 + 2 * n];
                b[nf][0] = bv.x; b[nf][1] = bv.y;
            }
            #pragma unroll
            for (int fm = 0; fm < 2; fm++) {
                int r0 = wm * 32 + fm * 16 + qrow;
                uint2 vA = *(const uint2*)&h1[r0 * H1ST + g * 8 + 2 * qk];
                uint2 vB = *(const uint2*)&h1[(r0 + 8) * H1ST + g * 8 + 2 * qk];
                #pragma unroll
                for (int nf = 0; nf < NF; nf++)
                    mma16(acc[fm][nf], vA.x, vB.x, vA.y, vB.y, b[nf][0], b[nf][1]);
            }
        }
        CP_WAIT0();
        __syncthreads();
    }

    // ---- layer 3: relu(h2).W3, quad reduce, combine ----
    float p0[2] = {0.f, 0.f}, p1[2] = {0.f, 0.f};
    #pragma unroll
    for (int fm = 0; fm < 2; fm++)
        #pragma unroll
        for (int nf = 0; nf < NF; nf++) {
            int c0 = nbase + nf * 8 + 2 * qk;
            float w30 = s_w3[c0], w31 = s_w3[c0 + 1];
            p0[fm] = fmaf(fmaxf(acc[fm][nf][0], 0.f), w30,
                     fmaf(fmaxf(acc[fm][nf][1], 0.f), w31, p0[fm]));
            p1[fm] = fmaf(fmaxf(acc[fm][nf][2], 0.f), w30,
                     fmaf(fmaxf(acc[fm][nf][3], 0.f), w31, p1[fm]));
        }
    #pragma unroll
    for (int fm = 0; fm < 2; fm++) {
        #pragma unroll
        for (int off = 1; off <= 2; off <<= 1) {
            p0[fm] += __shfl_xor_sync(0xffffffffu, p0[fm], off);
            p1[fm] += __shfl_xor_sync(0xffffffffu, p1[fm], off);
        }
    }
    if (qk == 0) {
        #pragma unroll
        for (int fm = 0; fm < 2; fm++) {
            int r0 = wm * 32 + fm * 16 + qrow;
            part[r0 * 2 + wn]       = p0[fm];
            part[(r0 + 8) * 2 + wn] = p1[fm];
        }
    }
    __syncthreads();

    if (tid < 128) {
        int il = tid >> 3, jl = tid & 7;
        float b3s = *(float*)(sm + OFF_B3);
        float sv = part[tid * 2] + part[tid * 2 + 1] + b3s;
        out[(i0 + il) * N_TOK + (j0 + jl)] =
            (msi[il] + msj[jl] + sv) * (1.f / 3.f);
    }
}

// ---------------------------------------------------------------------------
// pw_kernel: 128 pairs (16 i x 8 j) per block, fp16 m16n8k16, 2 blocks/SM.
// ---------------------------------------------------------------------------
__global__ __launch_bounds__(256, 2)
void pw_kernel(const float* __restrict__ G, const float* __restrict__ ms,
               const float* __restrict__ b2, const float* __restrict__ W3,
               const float* __restrict__ b3, float* __restrict__ out) {
    extern __shared__ char sm[];
    const uint32_t sb = (uint32_t)__cvta_generic_to_shared(sm);
    const int tid  = threadIdx.x;
    const int lane = tid & 31, wid = tid >> 5;
    const int wm = wid & 3, wn = wid >> 2;
    const int qrow = lane >> 2, qk = lane & 3;
    const int i0 = blockIdx.y * 16, j0 = blockIdx.x * 8;

    // stage GEMM1 weight chunk 0 (group)
    stage_chunk(sb + OFF_W, (const float4*)g_img1, tid);

    // small params
    float* s_b2 = (float*)(sm + OFF_B2);
    float* s_w3 = (float*)(sm + OFF_W3);
    if (tid < NP) {
        s_b2[tid] = (tid < HID) ? b2[tid] : 0.f;
        s_w3[tid] = (tid < HID) ? W3[tid] : 0.f;
    }
    if (tid < 16) ((float*)(sm + OFF_MSI))[tid] = ms[i0 + tid];
    if (tid < 8)  ((float*)(sm + OFF_MSJ))[tid] = ms[j0 + tid];
    if (tid == 0) *(float*)(sm + OFF_B3) = b3[0];

    // convert G rows to fp16 (gih stride 128; gjh stride 132) — unchanged
    uint32_t* gih = (uint32_t*)(sm + OFF_X);
    uint32_t* gjh = gih + 16 * 128;
    const float2* G2 = (const float2*)G;
    #pragma unroll
    for (int t = 0; t < 8; t++) {
        int idx = tid + t * 256, r = idx >> 7, w = idx & 127;
        float2 f = G2[(i0 + r) * 128 + w];
        gih[r * 128 + w] = packh2(f.x, f.y);
    }
    #pragma unroll
    for (int t = 0; t < 4; t++) {
        int idx = tid + t * 256, r = idx >> 7, w = idx & 127;
        float2 f = G2[(j0 + r) * 128 + w];
        gjh[r * 132 + w] = packh2(f.x, f.y);
    }
    __syncthreads();

    // build P: pair-interleaved within each 8-word group:
    // [w0,w4,w1,w5,w2,w6,w3,w7] at P[p*PST + G*8 + ...]
    {
        uint32_t* P = (uint32_t*)sm;
        int p = tid & 127, hh = tid >> 7;
        int il = p >> 3, jl = p & 7;
        #pragma unroll
        for (int g = 0; g < 8; g++) {
            int ka = hh * 64 + g * 8;
            uint4 va0 = *(uint4*)&gih[il * 128 + ka];
            uint4 va1 = *(uint4*)&gih[il * 128 + ka + 4];
            uint4 vb0 = *(uint4*)&gjh[jl * 132 + ka];
            uint4 vb1 = *(uint4*)&gjh[jl * 132 + ka + 4];
            uint32_t p0 = hmul2u(va0.x, vb0.x), p1 = hmul2u(va0.y, vb0.y);
            uint32_t p2 = hmul2u(va0.z, vb0.z), p3 = hmul2u(va0.w, vb0.w);
            uint32_t p4 = hmul2u(va1.x, vb1.x), p5 = hmul2u(va1.y, vb1.y);
            uint32_t p6 = hmul2u(va1.z, vb1.z), p7 = hmul2u(va1.w, vb1.w);
            uint32_t* dst = &P[p * PST + (hh * 8 + g) * 8];
            *(uint4*)&dst[0] = make_uint4(p0, p4, p1, p5);
            *(uint4*)&dst[4] = make_uint4(p2, p6, p3, p7);
        }
    }
    CP_WAIT0();          // weight chunk 0 resident
    __syncthreads();     // P ready; gih/gjh dead

    // sA/sB into X region via cp.async (consumed at h1 epilogue)
    {
        const float4* A4 = (const float4*)g_sA + i0 * (NP / 4);
        const float4* B4 = (const float4*)g_sB + j0 * (NP / 4);
        uint32_t dstA = sb + OFF_X, dstB = dstA + 16 * NP * 4;
        #pragma unroll
        for (int t = 0; t < 3; t++) {
            int idx = tid + t * 256;
            if (idx < 16 * (NP / 4)) cpasync16(dstA + idx * 16, A4 + idx);
        }
        #pragma unroll
        for (int t = 0; t < 2; t++) {
            int idx = tid + t * 256;
            if (idx < 8 * (NP / 4)) cpasync16(dstB + idx * 16, B4 + idx);
        }
        CP_COMMIT();
    }

    if (wn == 0) pw_body<10>(sm, sb, tid, wm, 0, qrow, qk, i0, j0, out);
    else         pw_body<9> (sm, sb, tid, wm, 1, qrow, qk, i0, j0, out);
}

// ---------------------------------------------------------------------------
extern "C" void kernel_launch(void* const* d_in, const int* in_sizes, int n_in,
                              void* d_out, int out_size) {
    const float* G  = (const float*)d_in[0];
    const float* ms = (const float*)d_in[1];
    const float* W1 = (const float*)d_in[2];
    const float* b1 = (const float*)d_in[3];
    const float* W2 = (const float*)d_in[4];
    const float* b2 = (const float*)d_in[5];
    const float* W3 = (const float*)d_in[6];
    const float* b3 = (const float*)d_in[7];
    float* out = (float*)d_out;

    cudaFuncSetAttribute(prep, cudaFuncAttributeMaxDynamicSharedMemorySize,
                         (int)sizeof(SmemAB));
    cudaFuncSetAttribute(pw_kernel, cudaFuncAttributeMaxDynamicSharedMemorySize,
                         PW_SMEM);

    prep<<<210, 256, sizeof(SmemAB)>>>(G, W1, W2, b1);
    pw_kernel<<<dim3(64, 32), 256, PW_SMEM>>>(G, ms, b2, W3, b3, out);
}

// round 16
// speedup vs baseline: 1.2769x; 1.2769x over previous
#include <cuda_runtime.h>
#include <cuda_fp16.h>
#include <cstdint>

#define N_TOK 512
#define E_DIM 256
#define HID   150
#define NP    152            // trimmed hidden dim (mult of 8)
#define WST   168            // weight image word stride
#define PST   132            // P word stride
#define H1ST  84             // h1 word stride
#define IMG1W (128 * WST)    // GEMM1 weights, 128 kpairs (K=256)
#define IMG2W (80  * WST)    // GEMM2 weights, 80 kpairs  (K=160)
#define CHUNK4 672           // 16 kpairs * 168 words / 4 float4 per chunk

__device__ float    g_sA[N_TOK * NP];
__device__ float    g_sB[N_TOK * NP];
__device__ uint32_t g_img1[IMG1W];
__device__ uint32_t g_img2[IMG2W];

// ---------------- SMEM layout (bytes) ----------------
#define OFF_P    0                       // P: 128 x 132 words (67584 B); h1 aliases
#define OFF_W    67584                   // weight double buffer 2 x 16 x 168 words
#define OFF_X    89088                   // gih/gjh (12416 B) then sA/sB (14592 B)
#define OFF_B2   103680
#define OFF_W3   104288
#define OFF_MSI  104896
#define OFF_MSJ  104960
#define OFF_PART 104992                  // 128 x 2 floats
#define OFF_B3   106016
#define PW_SMEM  106048

// ---------------- helpers ----------------
__device__ __forceinline__ uint32_t packh2(float lo, float hi) {
    __half2 h = __floats2half2_rn(lo, hi);
    return *reinterpret_cast<uint32_t*>(&h);
}
__device__ __forceinline__ uint32_t hmul2u(uint32_t a, uint32_t b) {
    __half2 r = __hmul2(*reinterpret_cast<__half2*>(&a), *reinterpret_cast<__half2*>(&b));
    return *reinterpret_cast<uint32_t*>(&r);
}
__device__ __forceinline__ void mma16(float* d, uint32_t a0, uint32_t a1,
                                      uint32_t a2, uint32_t a3,
                                      uint32_t b0, uint32_t b1) {
    asm volatile(
        "mma.sync.aligned.m16n8k16.row.col.f32.f16.f16.f32 "
        "{%0,%1,%2,%3}, {%4,%5,%6,%7}, {%8,%9}, {%0,%1,%2,%3};"
        : "+f"(d[0]), "+f"(d[1]), "+f"(d[2]), "+f"(d[3])
        : "r"(a0), "r"(a1), "r"(a2), "r"(a3), "r"(b0), "r"(b1));
}
__device__ __forceinline__ void cpasync16(uint32_t dst, const float4* src) {
    asm volatile("cp.async.cg.shared.global [%0], [%1], 16;" :: "r"(dst), "l"(src));
}
#define CP_COMMIT() asm volatile("cp.async.commit_group;")
#define CP_WAIT0()  asm volatile("cp.async.wait_group 0;" ::: "memory")

__device__ __forceinline__ void stage_chunk(uint32_t smem_dst, const float4* src, int tid) {
    #pragma unroll
    for (int t = 0; t < 3; t++) {
        int idx = tid + t * 256;
        if (idx < CHUNK4) cpasync16(smem_dst + idx * 16, src + idx);
    }
    CP_COMMIT();
}

// ---------------------------------------------------------------------------
// prep: one wave, 170 blocks x 512 threads.
//   blocks 0..127 : sA/sB precompute, split-K x2:
//       tx = tid&31 (5 cols), ty = (tid>>5)&7 (row), kh = tid>>8 (K-half)
//       kh=0 sums k 0..127 (+bias), kh=1 sums k 128..255 -> SMEM partial,
//       kh=0 adds partial and stores. fp32 throughout.
//   blocks 128..169: fp16 weight image build (42 blocks x 512 = 21504 words)
// ---------------------------------------------------------------------------
struct SmemAB {
    float g[8][E_DIM];       //  8192 B
    float w[2][32][160];     // 40960 B  (per-K-half weight tile)
    float partial[8][160];   //  5120 B
};

__global__ __launch_bounds__(512, 2)
void prep(const float* __restrict__ G, const float* __restrict__ W1,
          const float* __restrict__ W2, const float* __restrict__ b1) {
    const int bid = blockIdx.x, tid = threadIdx.x;

    if (bid >= 128) {
        // ---- weight image build (identical formulas to R14) ----
        int idx = (bid - 128) * 512 + tid;
        if (idx < IMG1W) {
            int kp = idx / WST, n = idx - kp * WST;
            float lo = 0.f, hi = 0.f;
            if (n < HID) {
                lo = W1[(2 * E_DIM + 2 * kp)     * HID + n];
                hi = W1[(2 * E_DIM + 2 * kp + 1) * HID + n];
            }
            g_img1[idx] = packh2(lo, hi);
        }
        if (idx < IMG2W) {
            int kp = idx / WST, n = idx - kp * WST;
            float lo = 0.f, hi = 0.f;
            if (n < HID) {
                if (2 * kp     < HID) lo = W2[(2 * kp)     * HID + n];
                if (2 * kp + 1 < HID) hi = W2[(2 * kp + 1) * HID + n];
            }
            g_img2[idx] = packh2(lo, hi);
        }
        return;
    }

    // ---- sA/sB precompute: 8 rows/block, split-K x2 ----
    extern __shared__ char smemraw[];
    SmemAB& s = *reinterpret_cast<SmemAB*>(smemraw);
    const int tx = tid & 31, ty = (tid >> 5) & 7, kh = tid >> 8;
    const int r0 = (bid >> 1) * 8, variant = bid & 1;
    const float* W = W1 + variant * E_DIM * HID;
    float* outbuf = variant ? g_sB : g_sA;

    for (int idx = tid; idx < 8 * E_DIM; idx += 512)
        s.g[idx >> 8][idx & 255] = G[(r0 + (idx >> 8)) * E_DIM + (idx & 255)];

    float acc[5];
    #pragma unroll
    for (int n = 0; n < 5; n++) {
        int h = tx * 5 + n;
        acc[n] = (kh == 0 && variant == 0 && h < HID) ? b1[h] : 0.f;
    }
    // each K-half: 4 tiles of 32
    for (int step = 0; step < 4; step++) {
        int kk = kh * 128 + step * 32;
        __syncthreads();
        {   // each half (256 threads) loads its own 32x160 tile
            int t8 = tid & 255;
            for (int idx = t8; idx < 32 * 160; idx += 256) {
                int r = idx / 160, c = idx - r * 160;
                s.w[kh][r][c] = (c < HID) ? W[(kk + r) * HID + c] : 0.f;
            }
        }
        __syncthreads();
        #pragma unroll 8
        for (int e = 0; e < 32; e++) {
            float a = s.g[ty][kk + e];
            float w[5];
            #pragma unroll
            for (int n = 0; n < 5; n++) w[n] = s.w[kh][e][tx * 5 + n];
            #pragma unroll
            for (int n = 0; n < 5; n++)
                acc[n] = fmaf(a, w[n], acc[n]);
        }
    }
    if (kh == 1) {
        #pragma unroll
        for (int n = 0; n < 5; n++)
            s.partial[ty][tx * 5 + n] = acc[n];
    }
    __syncthreads();
    if (kh == 0) {
        int r = r0 + ty;
        #pragma unroll
        for (int n = 0; n < 5; n++) {
            int h = tx * 5 + n;
            if (h < NP) outbuf[r * NP + h] = acc[n] + s.partial[ty][h];
        }
    }
}

// ---------------------------------------------------------------------------
// pw_body: templated on NF (n8 fragments per warp): wn=0 -> 10, wn=1 -> 9.
// (byte-identical logic to round 10/12/14)
// ---------------------------------------------------------------------------
template<int NF>
__device__ __forceinline__ void pw_body(
    char* sm, uint32_t sb, int tid, int wm, int wn, int qrow, int qk,
    int i0, int j0, float* __restrict__ out)
{
    uint32_t* P  = (uint32_t*)sm;           // GEMM1 A operand (fp16 products)
    uint32_t* h1 = (uint32_t*)sm;           // aliases P after GEMM1, stride H1ST
    float* sA   = (float*)(sm + OFF_X);
    float* sB   = sA + 16 * NP;
    float* s_b2 = (float*)(sm + OFF_B2);
    float* s_w3 = (float*)(sm + OFF_W3);
    float* msi  = (float*)(sm + OFF_MSI);
    float* msj  = (float*)(sm + OFF_MSJ);
    float* part = (float*)(sm + OFF_PART);
    const int nbase = wn * 80;
    const uint32_t wsm[2] = { sb + OFF_W, sb + OFF_W + 16 * WST * 4 };

    float acc[2][NF][4];
    #pragma unroll
    for (int fm = 0; fm < 2; fm++)
        #pragma unroll
        for (int nf = 0; nf < NF; nf++)
            #pragma unroll
            for (int q = 0; q < 4; q++) acc[fm][nf][q] = 0.f;

    const float4* img1_4 = (const float4*)g_img1;
    const float4* img2_4 = (const float4*)g_img2;

    // ---- GEMM1: acc = P @ W1c^T, K=256 = 8 chunks x 2 k16-tiles ----
    for (int c = 0; c < 8; c++) {
        stage_chunk(wsm[(c + 1) & 1],
                    (c < 7) ? (img1_4 + (c + 1) * CHUNK4) : img2_4, tid);
        const uint32_t* wb = (const uint32_t*)(sm + OFF_W) + (c & 1) * 16 * WST;
        #pragma unroll
        for (int t = 0; t < 2; t++) {
            int kw = (c * 2 + t) * 8;
            uint32_t b[NF][2];
            #pragma unroll
            for (int nf = 0; nf < NF; nf++) {
                int n = nbase + nf * 8 + qrow;
                b[nf][0] = wb[(t * 8 + qk) * WST + n];
                b[nf][1] = wb[(t * 8 + qk + 4) * WST + n];
            }
            #pragma unroll
            for (int fm = 0; fm < 2; fm++) {
                int rA = (wm * 32 + fm * 16 + qrow) * PST + kw + qk;
                uint32_t a0 = P[rA], a1 = P[rA + 8 * PST];
                uint32_t a2 = P[rA + 4], a3 = P[rA + 8 * PST + 4];
                #pragma unroll
                for (int nf = 0; nf < NF; nf++)
                    mma16(acc[fm][nf], a0, a1, a2, a3, b[nf][0], b[nf][1]);
            }
        }
        CP_WAIT0();
        __syncthreads();
    }

    // ---- h1 = relu(acc + sA_i + sB_j) as half2; re-init acc = b2 ----
    #pragma unroll
    for (int fm = 0; fm < 2; fm++) {
        int r0 = wm * 32 + fm * 16 + qrow, r1 = r0 + 8;
        int il0 = wm * 4 + fm * 2;
        #pragma unroll
        for (int nf = 0; nf < NF; nf++) {
            int c0 = nbase + nf * 8 + 2 * qk, c1 = c0 + 1;
            int word = wn * 40 + nf * 4 + qk;
            float sb0 = sB[qrow * NP + c0], sb1 = sB[qrow * NP + c1];
            float v00 = acc[fm][nf][0] + sA[il0 * NP + c0] + sb0;
            float v01 = acc[fm][nf][1] + sA[il0 * NP + c1] + sb1;
            float v10 = acc[fm][nf][2] + sA[(il0 + 1) * NP + c0] + sb0;
            float v11 = acc[fm][nf][3] + sA[(il0 + 1) * NP + c1] + sb1;
            h1[r0 * H1ST + word] = packh2(fmaxf(v00, 0.f), fmaxf(v01, 0.f));
            h1[r1 * H1ST + word] = packh2(fmaxf(v10, 0.f), fmaxf(v11, 0.f));
            float w0 = s_b2[c0], w1 = s_b2[c1];
            acc[fm][nf][0] = w0; acc[fm][nf][1] = w1;
            acc[fm][nf][2] = w0; acc[fm][nf][3] = w1;
        }
    }
    {   // zero pad words 76..79 (cols 152..159)
        int r = wm * 32 + (tid & 31);
        *(uint4*)&h1[r * H1ST + 76] = make_uint4(0, 0, 0, 0);
    }
    __syncthreads();   // h1 visible; w buf0 already holds img2 chunk 0

    // ---- GEMM2: acc += h1 @ W2^T, K=160 = 5 chunks x 2 k16-tiles ----
    for (int c = 0; c < 5; c++) {
        if (c < 4) stage_chunk(wsm[(c + 1) & 1], img2_4 + (c + 1) * CHUNK4, tid);
        const uint32_t* wb = (const uint32_t*)(sm + OFF_W) + (c & 1) * 16 * WST;
        #pragma unroll
        for (int t = 0; t < 2; t++) {
            int kw = (c * 2 + t) * 8;
            uint32_t b[NF][2];
            #pragma unroll
            for (int nf = 0; nf < NF; nf++) {
                int n = nbase + nf * 8 + qrow;
                b[nf][0] = wb[(t * 8 + qk) * WST + n];
                b[nf][1] = wb[(t * 8 + qk + 4) * WST + n];
            }
            #pragma unroll
            for (int fm = 0; fm < 2; fm++) {
                int r0 = wm * 32 + fm * 16 + qrow;
                uint32_t a0 = h1[r0 * H1ST + kw + qk];
                uint32_t a1 = h1[(r0 + 8) * H1ST + kw + qk];
                uint32_t a2 = h1[r0 * H1ST + kw + qk + 4];
                uint32_t a3 = h1[(r0 + 8) * H1ST + kw + qk + 4];
                #pragma unroll
                for (int nf = 0; nf < NF; nf++)
                    mma16(acc[fm][nf], a0, a1, a2, a3, b[nf][0], b[nf][1]);
            }
        }
        CP_WAIT0();
        __syncthreads();
    }

    // ---- layer 3: relu(h2).W3, quad reduce, combine ----
    float p0[2] = {0.f, 0.f}, p1[2] = {0.f, 0.f};
    #pragma unroll
    for (int fm = 0; fm < 2; fm++)
        #pragma unroll
        for (int nf = 0; nf < NF; nf++) {
            int c0 = nbase + nf * 8 + 2 * qk;
            float w30 = s_w3[c0], w31 = s_w3[c0 + 1];
            p0[fm] = fmaf(fmaxf(acc[fm][nf][0], 0.f), w30,
                     fmaf(fmaxf(acc[fm][nf][1], 0.f), w31, p0[fm]));
            p1[fm] = fmaf(fmaxf(acc[fm][nf][2], 0.f), w30,
                     fmaf(fmaxf(acc[fm][nf][3], 0.f), w31, p1[fm]));
        }
    #pragma unroll
    for (int fm = 0; fm < 2; fm++) {
        #pragma unroll
        for (int off = 1; off <= 2; off <<= 1) {
            p0[fm] += __shfl_xor_sync(0xffffffffu, p0[fm], off);
            p1[fm] += __shfl_xor_sync(0xffffffffu, p1[fm], off);
        }
    }
    if (qk == 0) {
        #pragma unroll
        for (int fm = 0; fm < 2; fm++) {
            int r0 = wm * 32 + fm * 16 + qrow;
            part[r0 * 2 + wn]       = p0[fm];
            part[(r0 + 8) * 2 + wn] = p1[fm];
        }
    }
    __syncthreads();

    if (tid < 128) {
        int il = tid >> 3, jl = tid & 7;
        float b3s = *(float*)(sm + OFF_B3);
        float sv = part[tid * 2] + part[tid * 2 + 1] + b3s;
        out[(i0 + il) * N_TOK + (j0 + jl)] =
            (msi[il] + msj[jl] + sv) * (1.f / 3.f);
    }
}

// ---------------------------------------------------------------------------
// pw_kernel: 128 pairs (16 i x 8 j) per block, fp16 m16n8k16, 2 blocks/SM.
// (byte-identical logic to round 10/12/14)
// ---------------------------------------------------------------------------
__global__ __launch_bounds__(256, 2)
void pw_kernel(const float* __restrict__ G, const float* __restrict__ ms,
               const float* __restrict__ b2, const float* __restrict__ W3,
               const float* __restrict__ b3, float* __restrict__ out) {
    extern __shared__ char sm[];
    const uint32_t sb = (uint32_t)__cvta_generic_to_shared(sm);
    const int tid  = threadIdx.x;
    const int lane = tid & 31, wid = tid >> 5;
    const int wm = wid & 3, wn = wid >> 2;
    const int qrow = lane >> 2, qk = lane & 3;
    const int i0 = blockIdx.y * 16, j0 = blockIdx.x * 8;

    // stage GEMM1 weight chunk 0 (group)
    stage_chunk(sb + OFF_W, (const float4*)g_img1, tid);

    // small params
    float* s_b2 = (float*)(sm + OFF_B2);
    float* s_w3 = (float*)(sm + OFF_W3);
    if (tid < NP) {
        s_b2[tid] = (tid < HID) ? b2[tid] : 0.f;
        s_w3[tid] = (tid < HID) ? W3[tid] : 0.f;
    }
    if (tid < 16) ((float*)(sm + OFF_MSI))[tid] = ms[i0 + tid];
    if (tid < 8)  ((float*)(sm + OFF_MSJ))[tid] = ms[j0 + tid];
    if (tid == 0) *(float*)(sm + OFF_B3) = b3[0];

    // convert G rows to fp16 (gih stride 128 broadcast-read; gjh stride 132)
    uint32_t* gih = (uint32_t*)(sm + OFF_X);
    uint32_t* gjh = gih + 16 * 128;
    const float2* G2 = (const float2*)G;
    #pragma unroll
    for (int t = 0; t < 8; t++) {
        int idx = tid + t * 256, r = idx >> 7, w = idx & 127;
        float2 f = G2[(i0 + r) * 128 + w];
        gih[r * 128 + w] = packh2(f.x, f.y);
    }
    #pragma unroll
    for (int t = 0; t < 4; t++) {
        int idx = tid + t * 256, r = idx >> 7, w = idx & 127;
        float2 f = G2[(j0 + r) * 128 + w];
        gjh[r * 132 + w] = packh2(f.x, f.y);
    }
    __syncthreads();

    // build P: 128 pairs x 128 half2 words (fragment-ready, stride PST)
    {
        uint32_t* P = (uint32_t*)sm;
        int p = tid & 127, hh = tid >> 7;
        int il = p >> 3, jl = p & 7;
        #pragma unroll
        for (int q = 0; q < 16; q++) {
            int ka = hh * 64 + q * 4;
            uint4 va = *(uint4*)&gih[il * 128 + ka];
            uint4 vb = *(uint4*)&gjh[jl * 132 + ka];
            uint4 o;
            o.x = hmul2u(va.x, vb.x);
            o.y = hmul2u(va.y, vb.y);
            o.z = hmul2u(va.z, vb.z);
            o.w = hmul2u(va.w, vb.w);
            *(uint4*)&P[p * PST + ka] = o;
        }
    }
    CP_WAIT0();          // weight chunk 0 resident
    __syncthreads();     // P ready; gih/gjh dead

    // sA/sB into X region via cp.async (consumed at h1 epilogue; first
    // in-loop CP_WAIT0 covers it)
    {
        const float4* A4 = (const float4*)g_sA + i0 * (NP / 4);
        const float4* B4 = (const float4*)g_sB + j0 * (NP / 4);
        uint32_t dstA = sb + OFF_X, dstB = dstA + 16 * NP * 4;
        #pragma unroll
        for (int t = 0; t < 3; t++) {
            int idx = tid + t * 256;
            if (idx < 16 * (NP / 4)) cpasync16(dstA + idx * 16, A4 + idx);
        }
        #pragma unroll
        for (int t = 0; t < 2; t++) {
            int idx = tid + t * 256;
            if (idx < 8 * (NP / 4)) cpasync16(dstB + idx * 16, B4 + idx);
        }
        CP_COMMIT();
    }

    if (wn == 0) pw_body<10>(sm, sb, tid, wm, 0, qrow, qk, i0, j0, out);
    else         pw_body<9> (sm, sb, tid, wm, 1, qrow, qk, i0, j0, out);
}

// ---------------------------------------------------------------------------
extern "C" void kernel_launch(void* const* d_in, const int* in_sizes, int n_in,
                              void* d_out, int out_size) {
    const float* G  = (const float*)d_in[0];
    const float* ms = (const float*)d_in[1];
    const float* W1 = (const float*)d_in[2];
    const float* b1 = (const float*)d_in[3];
    const float* W2 = (const float*)d_in[4];
    const float* b2 = (const float*)d_in[5];
    const float* W3 = (const float*)d_in[6];
    const float* b3 = (const float*)d_in[7];
    float* out = (float*)d_out;

    cudaFuncSetAttribute(prep, cudaFuncAttributeMaxDynamicSharedMemorySize,
                         (int)sizeof(SmemAB));
    cudaFuncSetAttribute(pw_kernel, cudaFuncAttributeMaxDynamicSharedMemorySize,
                         PW_SMEM);

    prep<<<170, 512, sizeof(SmemAB)>>>(G, W1, W2, b1);
    pw_kernel<<<dim3(64, 32), 256, PW_SMEM>>>(G, ms, b2, W3, b3, out);
}